// round 7
// baseline (speedup 1.0000x reference)
#include <cuda_runtime.h>
#include <cstdint>

// Problem constants
#define POOL 7
#define NUM_ROIS 256
#define H_IMG 128
#define W_IMG 128
#define SCALE (1.0f / 16.0f)

// One CTA per (roi, cell). Reads go through cp.async.bulk (bulk-async copy,
// bypasses L1tex and warp-issue) into SMEM; compute from SMEM; STG.128 out.
// Dead corners (lerp weight exactly 0, or clamped-duplicate coordinate) are
// simply not copied — consumers pointer-select the live buffer. Arithmetic
// is bit-identical to the reference.
__global__ void __launch_bounds__(128, 8)
roi_pool_kernel(const float* __restrict__ img,
                const float* __restrict__ rois,
                float* __restrict__ out)
{
    __shared__ alignas(128) float smbuf[4][1024];   // 16 KB: v00,v01,v10,v11
    __shared__ alignas(8) unsigned long long mbar;

    const int cell = blockIdx.x;   // 0..48
    const int roi  = blockIdx.y;   // 0..255
    const int iy   = cell / POOL;
    const int ix   = cell % POOL;

    const float4 r = *(const float4*)(rois + roi * 4);
    const int x0 = (int)(r.x * SCALE);
    const int y0 = (int)(r.y * SCALE);
    const int w  = (int)(r.z * SCALE);
    const int h  = (int)(r.w * SCALE);

    // Match reference arithmetic order exactly
    const float sy = (float)iy * ((float)h / (float)POOL);
    const float sx = (float)ix * ((float)w / (float)POOL);
    const float fy = floorf(sy);
    const float fx = floorf(sx);
    const float ty = sy - fy;
    const float tx = sx - fx;
    const int y_lo = (int)fy;
    const int x_lo = (int)fx;
    const int y_hi = min(y_lo + 1, max(h - 1, 0));
    const int x_hi = min(x_lo + 1, max(w - 1, 0));
    const int gy0 = min(max(y0 + y_lo, 0), H_IMG - 1);
    const int gy1 = min(max(y0 + y_hi, 0), H_IMG - 1);
    const int gx0 = min(max(x0 + x_lo, 0), W_IMG - 1);
    const int gx1 = min(max(x0 + x_hi, 0), W_IMG - 1);

    // Live-corner predicates (uniform across CTA).
    // needx==false => x-lerp contributes nothing new (weight 0 or same pixel).
    const bool needx = (tx != 0.0f) && (gx1 != gx0);
    const bool needy = (ty != 0.0f) && (gy1 != gy0);

    const int tid = threadIdx.x;
    const uint32_t mb = (uint32_t)__cvta_generic_to_shared(&mbar);

    if (tid == 0) {
        asm volatile("mbarrier.init.shared.b64 [%0], %1;"
                     :: "r"(mb), "r"(1u) : "memory");
    }
    __syncthreads();

    if (tid == 0) {
        const uint32_t nbuf = (1u + (uint32_t)needx) * (1u + (uint32_t)needy);
        asm volatile("mbarrier.arrive.expect_tx.shared.b64 _, [%0], %1;"
                     :: "r"(mb), "r"(nbuf * 4096u) : "memory");

        const float* p00 = img + ((size_t)(gy0 * W_IMG + gx0) << 10);
        const float* p01 = img + ((size_t)(gy0 * W_IMG + gx1) << 10);
        const float* p10 = img + ((size_t)(gy1 * W_IMG + gx0) << 10);
        const float* p11 = img + ((size_t)(gy1 * W_IMG + gx1) << 10);

        const uint32_t d0 = (uint32_t)__cvta_generic_to_shared(smbuf[0]);
        const uint32_t d1 = (uint32_t)__cvta_generic_to_shared(smbuf[1]);
        const uint32_t d2 = (uint32_t)__cvta_generic_to_shared(smbuf[2]);
        const uint32_t d3 = (uint32_t)__cvta_generic_to_shared(smbuf[3]);

        asm volatile(
            "cp.async.bulk.shared::cluster.global.mbarrier::complete_tx::bytes "
            "[%0], [%1], %2, [%3];"
            :: "r"(d0), "l"(p00), "r"(4096u), "r"(mb) : "memory");
        if (needx)
            asm volatile(
                "cp.async.bulk.shared::cluster.global.mbarrier::complete_tx::bytes "
                "[%0], [%1], %2, [%3];"
                :: "r"(d1), "l"(p01), "r"(4096u), "r"(mb) : "memory");
        if (needy)
            asm volatile(
                "cp.async.bulk.shared::cluster.global.mbarrier::complete_tx::bytes "
                "[%0], [%1], %2, [%3];"
                :: "r"(d2), "l"(p10), "r"(4096u), "r"(mb) : "memory");
        if (needx && needy)
            asm volatile(
                "cp.async.bulk.shared::cluster.global.mbarrier::complete_tx::bytes "
                "[%0], [%1], %2, [%3];"
                :: "r"(d3), "l"(p11), "r"(4096u), "r"(mb) : "memory");
    }

    // All threads wait for the bulk copies (parity 0: barrier used once/launch)
    asm volatile(
        "{\n\t"
        ".reg .pred P;\n\t"
        "WAIT_%=:\n\t"
        "mbarrier.try_wait.parity.acquire.cta.shared::cta.b64 P, [%0], %1;\n\t"
        "@!P bra WAIT_%=;\n\t"
        "}"
        :: "r"(mb), "r"(0u) : "memory");

    // Pointer-select live buffers (dead corner -> alias of live one; exact:
    // v + 0*(x - v) == v, and clamped corners are the same pixel anyway).
    const float4* s00 = (const float4*)smbuf[0];
    const float4* s01 = needx ? (const float4*)smbuf[1] : (const float4*)smbuf[0];
    const float4* s10 = needy ? (const float4*)smbuf[2] : (const float4*)smbuf[0];
    const float4* s11 = needx ? (needy ? (const float4*)smbuf[3] : (const float4*)smbuf[1])
                              : (needy ? (const float4*)smbuf[2] : (const float4*)smbuf[0]);

    float4* out4 = (float4*)out;
    const size_t obase = ((size_t)(roi * (POOL * POOL) + cell)) << 8;

    #pragma unroll
    for (int k = 0; k < 2; k++) {
        const int c = tid + k * 128;   // float4 index 0..255

        const float4 v00 = s00[c];
        const float4 v01 = s01[c];
        const float4 v10 = s10[c];
        const float4 v11 = s11[c];

        float4 o;
        {
            float top = v00.x + tx * (v01.x - v00.x);
            float bot = v10.x + tx * (v11.x - v10.x);
            o.x = top + ty * (bot - top);
        }
        {
            float top = v00.y + tx * (v01.y - v00.y);
            float bot = v10.y + tx * (v11.y - v10.y);
            o.y = top + ty * (bot - top);
        }
        {
            float top = v00.z + tx * (v01.z - v00.z);
            float bot = v10.z + tx * (v11.z - v10.z);
            o.z = top + ty * (bot - top);
        }
        {
            float top = v00.w + tx * (v01.w - v00.w);
            float bot = v10.w + tx * (v11.w - v10.w);
            o.w = top + ty * (bot - top);
        }

        out4[obase + c] = o;
    }
}

extern "C" void kernel_launch(void* const* d_in, const int* in_sizes, int n_in,
                              void* d_out, int out_size)
{
    const float* img  = (const float*)d_in[0];
    const float* rois = (const float*)d_in[1];
    float* out = (float*)d_out;

    dim3 grid(POOL * POOL, NUM_ROIS);
    roi_pool_kernel<<<grid, 128>>>(img, rois, out);
}

// round 8
// speedup vs baseline: 1.0327x; 1.0327x over previous
#include <cuda_runtime.h>

// Problem constants
#define POOL 7
#define NUM_ROIS 256
#define H_IMG 128
#define W_IMG 128
#define C_IMG 1024
#define SCALE (1.0f / 16.0f)

// One CTA per (roi, cell), 256 threads, one float4 of channels per thread.
// R6 structure (branchless dead-corner address redirect) + STREAMING stores:
// out is written with st.global.cs (evict-first) so the 51 MB output stream
// does not evict the 64 MB img from L2. img then stays L2-resident across
// graph replays -> reads are L2 hits, DRAM carries only the write stream.
__global__ void __launch_bounds__(256, 8)
roi_pool_kernel(const float* __restrict__ img,
                const float* __restrict__ rois,
                float* __restrict__ out)
{
    const int cell = blockIdx.x;   // 0..48
    const int roi  = blockIdx.y;   // 0..255
    const int iy   = cell / POOL;
    const int ix   = cell % POOL;

    const float4 r = *(const float4*)(rois + roi * 4);
    const int x0 = (int)(r.x * SCALE);
    const int y0 = (int)(r.y * SCALE);
    const int w  = (int)(r.z * SCALE);
    const int h  = (int)(r.w * SCALE);

    // Match reference arithmetic order exactly
    const float sy = (float)iy * ((float)h / (float)POOL);
    const float sx = (float)ix * ((float)w / (float)POOL);
    const float fy = floorf(sy);
    const float fx = floorf(sx);
    const float ty = sy - fy;
    const float tx = sx - fx;
    const int y_lo = (int)fy;
    const int x_lo = (int)fx;
    const int y_hi = min(y_lo + 1, max(h - 1, 0));
    const int x_hi = min(x_lo + 1, max(w - 1, 0));
    const int gy0 = min(max(y0 + y_lo, 0), H_IMG - 1);
    int       gy1 = min(max(y0 + y_hi, 0), H_IMG - 1);
    const int gx0 = min(max(x0 + x_lo, 0), W_IMG - 1);
    int       gx1 = min(max(x0 + x_hi, 0), W_IMG - 1);

    // Branchless dead-load redirection (SEL): zero-weight corner -> alias of
    // the live corner (same L1 line, zero extra L2/DRAM bytes). Exact:
    // v + 0*(x - v) == v for finite data.
    gx1 = (tx != 0.0f) ? gx1 : gx0;
    gy1 = (ty != 0.0f) ? gy1 : gy0;

    const float4* p00 = (const float4*)(img + ((size_t)(gy0 * W_IMG + gx0) << 10));
    const float4* p01 = (const float4*)(img + ((size_t)(gy0 * W_IMG + gx1) << 10));
    const float4* p10 = (const float4*)(img + ((size_t)(gy1 * W_IMG + gx0) << 10));
    const float4* p11 = (const float4*)(img + ((size_t)(gy1 * W_IMG + gx1) << 10));

    const int c = threadIdx.x;  // float4 index 0..255

    const float4 v00 = p00[c];
    const float4 v01 = p01[c];
    const float4 v10 = p10[c];
    const float4 v11 = p11[c];

    float4 o;
    {
        float top = v00.x + tx * (v01.x - v00.x);
        float bot = v10.x + tx * (v11.x - v10.x);
        o.x = top + ty * (bot - top);
    }
    {
        float top = v00.y + tx * (v01.y - v00.y);
        float bot = v10.y + tx * (v11.y - v10.y);
        o.y = top + ty * (bot - top);
    }
    {
        float top = v00.z + tx * (v01.z - v00.z);
        float bot = v10.z + tx * (v11.z - v10.z);
        o.z = top + ty * (bot - top);
    }
    {
        float top = v00.w + tx * (v01.w - v00.w);
        float bot = v10.w + tx * (v11.w - v10.w);
        o.w = top + ty * (bot - top);
    }

    // Streaming (evict-first) store: keep out lines from displacing img in L2.
    float4* dst = (float4*)out + (((size_t)(roi * (POOL * POOL) + cell)) << 8) + c;
    __stcs(dst, o);
}

extern "C" void kernel_launch(void* const* d_in, const int* in_sizes, int n_in,
                              void* d_out, int out_size)
{
    const float* img  = (const float*)d_in[0];
    const float* rois = (const float*)d_in[1];
    float* out = (float*)d_out;

    dim3 grid(POOL * POOL, NUM_ROIS);
    roi_pool_kernel<<<grid, 256>>>(img, rois, out);
}